// round 1
// baseline (speedup 1.0000x reference)
#include <cuda_runtime.h>
#include <math.h>

#define DDIM   256
#define BATCH  128
#define SEQ    1024
#define NROWS  (BATCH*SEQ)          // 131072
#define NBLK_B 1024
#define NBLK_C 2048

// ---- scratch (static device globals; no allocation) ----
__device__ __align__(16) float g_part[8*BATCH*DDIM];   // pass-A partial sums [j][b][d]
__device__ __align__(16) float g_cb[BATCH*DDIM];       // per-batch centroids
__device__ __align__(16) float g_mean[DDIM];
__device__ __align__(16) float g_am[DDIM];             // add_origin(mean)
__device__ float g_ic;                                  // 1/(1+mean0)
__device__ __align__(16) float g_bpS[NBLK_B*DDIM];     // pass-B per-block sum(t)
__device__ __align__(16) float g_bpQ[NBLK_B*DDIM];     // pass-B per-block sum(t^2)
__device__ __align__(16) float g_scale[DDIM];          // gamma / sqrt(var+eps)
__device__ __align__(16) float g_ab[DDIM];             // add_origin(beta)
__device__ float g_ib;                                  // 1/(1+beta0)

__device__ __forceinline__ float warpsum(float v) {
    v += __shfl_xor_sync(0xffffffffu, v, 16);
    v += __shfl_xor_sync(0xffffffffu, v, 8);
    v += __shfl_xor_sync(0xffffffffu, v, 4);
    v += __shfl_xor_sync(0xffffffffu, v, 2);
    v += __shfl_xor_sync(0xffffffffu, v, 1);
    return v;
}

// ---------------------------------------------------------------------------
// Pass A: per-(chunk j, batch b) feature sums over 128 rows of S.
// grid (8, 128), block 256. Thread d sums x[b, j*128 + s, d].
// ---------------------------------------------------------------------------
__global__ void __launch_bounds__(256) passA_kernel(const float* __restrict__ x) {
    const int j = blockIdx.x;
    const int b = blockIdx.y;
    const int d = threadIdx.x;
    const float* p = x + ((size_t)b*SEQ + (size_t)j*128) * DDIM + d;
    float a0 = 0.f, a1 = 0.f, a2 = 0.f, a3 = 0.f;
    #pragma unroll 4
    for (int s = 0; s < 128; s += 4) {
        a0 += p[(s+0)*DDIM];
        a1 += p[(s+1)*DDIM];
        a2 += p[(s+2)*DDIM];
        a3 += p[(s+3)*DDIM];
    }
    g_part[((size_t)(j*BATCH + b))*DDIM + d] = (a0+a1) + (a2+a3);
}

// ---------------------------------------------------------------------------
// A2: per-batch centroid, then centroid over batch -> g_mean, g_am, g_ic.
// single block of 1024 threads (32 warps).
// ---------------------------------------------------------------------------
__global__ void __launch_bounds__(1024) a2_kernel() {
    __shared__ float red[DDIM];
    const int tid  = threadIdx.x;
    const int lane = tid & 31;
    const int warp = tid >> 5;

    // phase 1: warp handles batches b = warp, warp+32, ...
    for (int b = warp; b < BATCH; b += 32) {
        float4 vA = make_float4(0.f,0.f,0.f,0.f);
        float4 vB = make_float4(0.f,0.f,0.f,0.f);
        #pragma unroll
        for (int j = 0; j < 8; j++) {
            const float4* sp = reinterpret_cast<const float4*>(g_part + (size_t)(j*BATCH + b)*DDIM);
            float4 a = sp[lane];
            float4 c = sp[lane+32];
            vA.x += a.x; vA.y += a.y; vA.z += a.z; vA.w += a.w;
            vB.x += c.x; vB.y += c.y; vB.z += c.z; vB.w += c.w;
        }
        const float inv = 1.0f / (float)SEQ;
        vA.x *= inv; vA.y *= inv; vA.z *= inv; vA.w *= inv;
        vB.x *= inv; vB.y *= inv; vB.z *= inv; vB.w *= inv;
        float p = (lane == 0) ? -vA.x*vA.x : vA.x*vA.x;
        p += vA.y*vA.y + vA.z*vA.z + vA.w*vA.w;
        p += vB.x*vB.x + vB.y*vB.y + vB.z*vB.z + vB.w*vB.w;
        float l = warpsum(p);                       // linner(avg, avg)
        float dn = rsqrtf(fmaxf(fabsf(l), 1e-8f));  // 1/denom
        float4* cp = reinterpret_cast<float4*>(g_cb + (size_t)b*DDIM);
        cp[lane]    = make_float4(vA.x*dn, vA.y*dn, vA.z*dn, vA.w*dn);
        cp[lane+32] = make_float4(vB.x*dn, vB.y*dn, vB.z*dn, vB.w*dn);
    }
    __syncthreads();

    // phase 2: mean over batch of centroids, normalize -> g_mean
    float a = 0.f;
    if (tid < DDIM) {
        for (int b = 0; b < BATCH; b++) a += g_cb[(size_t)b*DDIM + tid];
        a *= (1.0f / (float)BATCH);
        red[tid] = (tid == 0) ? -a*a : a*a;
    }
    __syncthreads();
    for (int off = 128; off > 0; off >>= 1) {
        if (tid < off) red[tid] += red[tid + off];
        __syncthreads();
    }
    if (tid < DDIM) {
        float dn = rsqrtf(fmaxf(fabsf(red[0]), 1e-8f));
        float mv = a * dn;
        g_mean[tid] = mv;
        g_am[tid]   = mv + ((tid == 0) ? 1.0f : 0.0f);
        if (tid == 0) g_ic = 1.0f / (1.0f + mv);
    }
}

// ---------------------------------------------------------------------------
// Pass B: per-feature Sum(t), Sum(t^2) over all rows,
// t = transp0back(mean, logmap(mean, x)). Warp-per-row, per-block partials.
// ---------------------------------------------------------------------------
__global__ void __launch_bounds__(256) passB_kernel(const float* __restrict__ x) {
    __shared__ float sS[8][DDIM];
    __shared__ float sQ[8][DDIM];
    const int lane = threadIdx.x & 31;
    const int wib  = threadIdx.x >> 5;
    const int gw   = blockIdx.x * 8 + wib;
    const int nw   = NBLK_B * 8;

    float m[8], am[8];
    {
        float4 v;
        v = reinterpret_cast<const float4*>(g_mean)[lane];    m[0]=v.x; m[1]=v.y; m[2]=v.z; m[3]=v.w;
        v = reinterpret_cast<const float4*>(g_mean)[lane+32]; m[4]=v.x; m[5]=v.y; m[6]=v.z; m[7]=v.w;
        v = reinterpret_cast<const float4*>(g_am)[lane];      am[0]=v.x; am[1]=v.y; am[2]=v.z; am[3]=v.w;
        v = reinterpret_cast<const float4*>(g_am)[lane+32];   am[4]=v.x; am[5]=v.y; am[6]=v.z; am[7]=v.w;
    }
    const float m0 = g_mean[0];
    const float ic = g_ic;

    float sm[8] = {0,0,0,0,0,0,0,0};
    float sq[8] = {0,0,0,0,0,0,0,0};

    for (int row = gw; row < NROWS; row += nw) {
        const float4* rp = reinterpret_cast<const float4*>(x) + (size_t)row * (DDIM/4);
        float xv[8];
        {
            float4 v = rp[lane];    xv[0]=v.x; xv[1]=v.y; xv[2]=v.z; xv[3]=v.w;
            v = rp[lane+32];        xv[4]=v.x; xv[5]=v.y; xv[6]=v.z; xv[7]=v.w;
        }
        float p = m[0]*xv[0];
        if (lane == 0) p = -p;
        #pragma unroll
        for (int k = 1; k < 8; k++) p += m[k]*xv[k];
        float l = warpsum(p);                              // linner(mean, x)
        float alpha = fmaxf(-l, 1.0f + 1e-7f);
        float x0 = __shfl_sync(0xffffffffu, xv[0], 0);
        float f = acoshf(alpha) * rsqrtf(alpha*alpha - 1.0f);
        float coef = f * (x0 - alpha*m0) * ic;
        #pragma unroll
        for (int k = 0; k < 8; k++) {
            float t = f*(xv[k] - alpha*m[k]) - coef*am[k];
            sm[k] += t;
            sq[k] += t*t;
        }
    }

    const int d0 = lane * 4;
    #pragma unroll
    for (int k = 0; k < 4; k++) {
        sS[wib][d0+k]     = sm[k];   sQ[wib][d0+k]     = sq[k];
        sS[wib][128+d0+k] = sm[4+k]; sQ[wib][128+d0+k] = sq[4+k];
    }
    __syncthreads();
    float accS = 0.f, accQ = 0.f;
    #pragma unroll
    for (int w = 0; w < 8; w++) { accS += sS[w][threadIdx.x]; accQ += sQ[w][threadIdx.x]; }
    g_bpS[(size_t)blockIdx.x*DDIM + threadIdx.x] = accS;
    g_bpQ[(size_t)blockIdx.x*DDIM + threadIdx.x] = accQ;
}

// ---------------------------------------------------------------------------
// B2: fold per-block partials -> scale[d]; precompute beta-derived constants.
// ---------------------------------------------------------------------------
__global__ void __launch_bounds__(256) finB_kernel(const float* __restrict__ beta,
                                                   const float* __restrict__ gamma) {
    const int d = threadIdx.x;
    float s = 0.f, q = 0.f;
    for (int b = 0; b < NBLK_B; b++) {
        s += g_bpS[(size_t)b*DDIM + d];
        q += g_bpQ[(size_t)b*DDIM + d];
    }
    const float invN = 1.0f / (float)NROWS;
    float mu  = s * invN;
    float var = q * invN - mu*mu;
    g_scale[d] = gamma[0] * rsqrtf(var + 1e-5f);   // gamma / sqrt(var + eps)
    float bv = beta[d];
    g_ab[d] = bv + ((d == 0) ? 1.0f : 0.0f);
    if (d == 0) g_ib = 1.0f / (1.0f + bv);
}

// ---------------------------------------------------------------------------
// Pass C: recompute t, scale, transp0(beta), expmap(beta) -> out.
// ---------------------------------------------------------------------------
__global__ void __launch_bounds__(256) passC_kernel(const float* __restrict__ x,
                                                    const float* __restrict__ beta,
                                                    float* __restrict__ out) {
    const int lane = threadIdx.x & 31;
    const int gw   = (blockIdx.x * blockDim.x + threadIdx.x) >> 5;
    const int nw   = (NBLK_C * 256) >> 5;

    float m[8], am[8], sc[8], bt[8], ab[8];
    {
        float4 v;
        v = reinterpret_cast<const float4*>(g_mean)[lane];     m[0]=v.x; m[1]=v.y; m[2]=v.z; m[3]=v.w;
        v = reinterpret_cast<const float4*>(g_mean)[lane+32];  m[4]=v.x; m[5]=v.y; m[6]=v.z; m[7]=v.w;
        v = reinterpret_cast<const float4*>(g_am)[lane];       am[0]=v.x; am[1]=v.y; am[2]=v.z; am[3]=v.w;
        v = reinterpret_cast<const float4*>(g_am)[lane+32];    am[4]=v.x; am[5]=v.y; am[6]=v.z; am[7]=v.w;
        v = reinterpret_cast<const float4*>(g_scale)[lane];    sc[0]=v.x; sc[1]=v.y; sc[2]=v.z; sc[3]=v.w;
        v = reinterpret_cast<const float4*>(g_scale)[lane+32]; sc[4]=v.x; sc[5]=v.y; sc[6]=v.z; sc[7]=v.w;
        v = reinterpret_cast<const float4*>(beta)[lane];       bt[0]=v.x; bt[1]=v.y; bt[2]=v.z; bt[3]=v.w;
        v = reinterpret_cast<const float4*>(beta)[lane+32];    bt[4]=v.x; bt[5]=v.y; bt[6]=v.z; bt[7]=v.w;
        v = reinterpret_cast<const float4*>(g_ab)[lane];       ab[0]=v.x; ab[1]=v.y; ab[2]=v.z; ab[3]=v.w;
        v = reinterpret_cast<const float4*>(g_ab)[lane+32];    ab[4]=v.x; ab[5]=v.y; ab[6]=v.z; ab[7]=v.w;
    }
    const float m0 = g_mean[0];
    const float ic = g_ic;
    const float ib = g_ib;

    for (int row = gw; row < NROWS; row += nw) {
        const float4* rp = reinterpret_cast<const float4*>(x) + (size_t)row * (DDIM/4);
        float xv[8];
        {
            float4 v = rp[lane];    xv[0]=v.x; xv[1]=v.y; xv[2]=v.z; xv[3]=v.w;
            v = rp[lane+32];        xv[4]=v.x; xv[5]=v.y; xv[6]=v.z; xv[7]=v.w;
        }
        // t = transp0back(mean, logmap(mean, x))
        float p = m[0]*xv[0];
        if (lane == 0) p = -p;
        #pragma unroll
        for (int k = 1; k < 8; k++) p += m[k]*xv[k];
        float l = warpsum(p);
        float alpha = fmaxf(-l, 1.0f + 1e-7f);
        float x0 = __shfl_sync(0xffffffffu, xv[0], 0);
        float f = acoshf(alpha) * rsqrtf(alpha*alpha - 1.0f);
        float coef = f * (x0 - alpha*m0) * ic;
        float w[8];
        #pragma unroll
        for (int k = 0; k < 8; k++)
            w[k] = (f*(xv[k] - alpha*m[k]) - coef*am[k]) * sc[k];

        // transp0(beta, w)
        float p2 = bt[0]*w[0];
        if (lane == 0) p2 = -p2;
        #pragma unroll
        for (int k = 1; k < 8; k++) p2 += bt[k]*w[k];
        float lb = warpsum(p2);                  // linner(beta, w)
        float c2 = lb * ib;
        #pragma unroll
        for (int k = 0; k < 8; k++) w[k] += c2*ab[k];

        // expmap(beta, w)
        float p3 = w[0]*w[0];
        if (lane == 0) p3 = -p3;
        #pragma unroll
        for (int k = 1; k < 8; k++) p3 += w[k]*w[k];
        float nn = warpsum(p3);                  // linner(w, w)
        float n  = sqrtf(fmaxf(nn, 1e-7f));
        float ch = coshf(n);
        float sh = sinhf(n) / n;

        float4* op = reinterpret_cast<float4*>(out) + (size_t)row * (DDIM/4);
        op[lane]    = make_float4(ch*bt[0] + sh*w[0], ch*bt[1] + sh*w[1],
                                  ch*bt[2] + sh*w[2], ch*bt[3] + sh*w[3]);
        op[lane+32] = make_float4(ch*bt[4] + sh*w[4], ch*bt[5] + sh*w[5],
                                  ch*bt[6] + sh*w[6], ch*bt[7] + sh*w[7]);
    }
}

// ---------------------------------------------------------------------------
extern "C" void kernel_launch(void* const* d_in, const int* in_sizes, int n_in,
                              void* d_out, int out_size) {
    const float* x     = (const float*)d_in[0];
    const float* beta  = (const float*)d_in[1];
    const float* gamma = (const float*)d_in[2];
    float* out = (float*)d_out;

    dim3 gA(8, BATCH);
    passA_kernel<<<gA, 256>>>(x);
    a2_kernel<<<1, 1024>>>();
    passB_kernel<<<NBLK_B, 256>>>(x);
    finB_kernel<<<1, 256>>>(beta, gamma);
    passC_kernel<<<NBLK_C, 256>>>(x, beta, out);
}

// round 2
// speedup vs baseline: 1.3133x; 1.3133x over previous
#include <cuda_runtime.h>
#include <math.h>

#define DDIM   256
#define BATCH  128
#define SEQ    1024
#define NROWS  (BATCH*SEQ)          // 131072
#define NBLK_B 1024
#define NBLK_C 2048

// ---- scratch (static device globals; no allocation) ----
__device__ __align__(16) float g_part[8*BATCH*DDIM];   // pass-A partial sums [j][b][d]
__device__ __align__(16) float g_cb[BATCH*DDIM];       // per-batch centroids
__device__ __align__(16) float g_mean[DDIM];
__device__ __align__(16) float g_am[DDIM];             // add_origin(mean)
__device__ float g_ic;                                  // 1/(1+mean0)
__device__ __align__(16) float g_bpS[NBLK_B*DDIM];     // pass-B per-block sum(t)
__device__ __align__(16) float g_bpQ[NBLK_B*DDIM];     // pass-B per-block sum(t^2)
__device__ __align__(16) float g_scale[DDIM];          // gamma / sqrt(var+eps)
__device__ __align__(16) float g_ab[DDIM];             // add_origin(beta)
__device__ float g_ib;                                  // 1/(1+beta0)

__device__ __forceinline__ float warpsum(float v) {
    v += __shfl_xor_sync(0xffffffffu, v, 16);
    v += __shfl_xor_sync(0xffffffffu, v, 8);
    v += __shfl_xor_sync(0xffffffffu, v, 4);
    v += __shfl_xor_sync(0xffffffffu, v, 2);
    v += __shfl_xor_sync(0xffffffffu, v, 1);
    return v;
}

// block-level sum of 256 values (one per thread); result valid on all threads.
__device__ __forceinline__ float blocksum256(float v, float* sh) {
    const int tid  = threadIdx.x;
    const int lane = tid & 31;
    const int warp = tid >> 5;
    float w = warpsum(v);
    if (lane == 0) sh[warp] = w;
    __syncthreads();
    float r = sh[0];
    #pragma unroll
    for (int i = 1; i < 8; i++) r += sh[i];
    return r;
}

// ---------------------------------------------------------------------------
// Pass A: per-(chunk j, batch b) feature sums over 128 rows of S.
// grid (8, 128), block 256. Thread d sums x[b, j*128 + s, d].
// ---------------------------------------------------------------------------
__global__ void __launch_bounds__(256) passA_kernel(const float* __restrict__ x) {
    const int j = blockIdx.x;
    const int b = blockIdx.y;
    const int d = threadIdx.x;
    const float* p = x + ((size_t)b*SEQ + (size_t)j*128) * DDIM + d;
    float a0 = 0.f, a1 = 0.f, a2 = 0.f, a3 = 0.f;
    #pragma unroll 4
    for (int s = 0; s < 128; s += 4) {
        a0 += p[(s+0)*DDIM];
        a1 += p[(s+1)*DDIM];
        a2 += p[(s+2)*DDIM];
        a3 += p[(s+3)*DDIM];
    }
    g_part[((size_t)(j*BATCH + b))*DDIM + d] = (a0+a1) + (a2+a3);
}

// ---------------------------------------------------------------------------
// A2a: per-batch centroid. grid 128 (one block per batch), block 256.
// ---------------------------------------------------------------------------
__global__ void __launch_bounds__(256) a2a_kernel() {
    __shared__ float sh[8];
    const int b = blockIdx.x;
    const int d = threadIdx.x;
    float a = 0.f;
    #pragma unroll
    for (int j = 0; j < 8; j++)
        a += g_part[(size_t)(j*BATCH + b)*DDIM + d];
    a *= (1.0f / (float)SEQ);
    float p = (d == 0) ? -a*a : a*a;
    float l = blocksum256(p, sh);                  // linner(avg, avg)
    float dn = rsqrtf(fmaxf(fabsf(l), 1e-8f));
    g_cb[(size_t)b*DDIM + d] = a * dn;
}

// ---------------------------------------------------------------------------
// A2b: centroid over batch of per-batch centroids -> g_mean, g_am, g_ic.
// single block 256 (reads 128KB, fully coalesced: inner index d contiguous).
// ---------------------------------------------------------------------------
__global__ void __launch_bounds__(256) a2b_kernel() {
    __shared__ float sh[8];
    const int d = threadIdx.x;
    float a = 0.f;
    #pragma unroll 8
    for (int b = 0; b < BATCH; b++) a += g_cb[(size_t)b*DDIM + d];
    a *= (1.0f / (float)BATCH);
    float p = (d == 0) ? -a*a : a*a;
    float l = blocksum256(p, sh);
    float dn = rsqrtf(fmaxf(fabsf(l), 1e-8f));
    float mv = a * dn;
    g_mean[d] = mv;
    g_am[d]   = mv + ((d == 0) ? 1.0f : 0.0f);
    if (d == 0) g_ic = 1.0f / (1.0f + mv);
}

// ---------------------------------------------------------------------------
// Pass B: per-feature Sum(t), Sum(t^2) over all rows,
// t = transp0back(mean, logmap(mean, x)). Warp-per-row, per-block partials.
// ---------------------------------------------------------------------------
__global__ void __launch_bounds__(256) passB_kernel(const float* __restrict__ x) {
    __shared__ float sS[8][DDIM];
    __shared__ float sQ[8][DDIM];
    const int lane = threadIdx.x & 31;
    const int wib  = threadIdx.x >> 5;
    const int gw   = blockIdx.x * 8 + wib;
    const int nw   = NBLK_B * 8;

    float m[8], am[8];
    {
        float4 v;
        v = reinterpret_cast<const float4*>(g_mean)[lane];    m[0]=v.x; m[1]=v.y; m[2]=v.z; m[3]=v.w;
        v = reinterpret_cast<const float4*>(g_mean)[lane+32]; m[4]=v.x; m[5]=v.y; m[6]=v.z; m[7]=v.w;
        v = reinterpret_cast<const float4*>(g_am)[lane];      am[0]=v.x; am[1]=v.y; am[2]=v.z; am[3]=v.w;
        v = reinterpret_cast<const float4*>(g_am)[lane+32];   am[4]=v.x; am[5]=v.y; am[6]=v.z; am[7]=v.w;
    }
    const float m0 = g_mean[0];
    const float ic = g_ic;

    float sm[8] = {0,0,0,0,0,0,0,0};
    float sq[8] = {0,0,0,0,0,0,0,0};

    for (int row = gw; row < NROWS; row += nw) {
        const float4* rp = reinterpret_cast<const float4*>(x) + (size_t)row * (DDIM/4);
        float xv[8];
        {
            float4 v = rp[lane];    xv[0]=v.x; xv[1]=v.y; xv[2]=v.z; xv[3]=v.w;
            v = rp[lane+32];        xv[4]=v.x; xv[5]=v.y; xv[6]=v.z; xv[7]=v.w;
        }
        float p = m[0]*xv[0];
        if (lane == 0) p = -p;
        #pragma unroll
        for (int k = 1; k < 8; k++) p += m[k]*xv[k];
        float l = warpsum(p);                              // linner(mean, x)
        float alpha = fmaxf(-l, 1.0f + 1e-7f);
        float x0 = __shfl_sync(0xffffffffu, xv[0], 0);
        float f = acoshf(alpha) * rsqrtf(alpha*alpha - 1.0f);
        float coef = f * (x0 - alpha*m0) * ic;
        #pragma unroll
        for (int k = 0; k < 8; k++) {
            float t = f*(xv[k] - alpha*m[k]) - coef*am[k];
            sm[k] += t;
            sq[k] += t*t;
        }
    }

    const int d0 = lane * 4;
    #pragma unroll
    for (int k = 0; k < 4; k++) {
        sS[wib][d0+k]     = sm[k];   sQ[wib][d0+k]     = sq[k];
        sS[wib][128+d0+k] = sm[4+k]; sQ[wib][128+d0+k] = sq[4+k];
    }
    __syncthreads();
    float accS = 0.f, accQ = 0.f;
    #pragma unroll
    for (int w = 0; w < 8; w++) { accS += sS[w][threadIdx.x]; accQ += sQ[w][threadIdx.x]; }
    g_bpS[(size_t)blockIdx.x*DDIM + threadIdx.x] = accS;
    g_bpQ[(size_t)blockIdx.x*DDIM + threadIdx.x] = accQ;
}

// ---------------------------------------------------------------------------
// finB: fold per-block partials -> scale[d]. grid 256 (one feature per block),
// 256 threads tree-reduce the 1024 block partials. Also beta constants.
// ---------------------------------------------------------------------------
__global__ void __launch_bounds__(256) finB_kernel(const float* __restrict__ beta,
                                                   const float* __restrict__ gamma) {
    __shared__ float shS[8];
    __shared__ float shQ[8];
    const int d   = blockIdx.x;
    const int tid = threadIdx.x;
    const int lane = tid & 31;
    const int warp = tid >> 5;

    float s = 0.f, q = 0.f;
    #pragma unroll
    for (int i = 0; i < NBLK_B/256; i++) {
        int b = i*256 + tid;
        s += g_bpS[(size_t)b*DDIM + d];
        q += g_bpQ[(size_t)b*DDIM + d];
    }
    float ws = warpsum(s);
    float wq = warpsum(q);
    if (lane == 0) { shS[warp] = ws; shQ[warp] = wq; }
    __syncthreads();
    if (tid == 0) {
        float S = shS[0], Q = shQ[0];
        #pragma unroll
        for (int i = 1; i < 8; i++) { S += shS[i]; Q += shQ[i]; }
        const float invN = 1.0f / (float)NROWS;
        float mu  = S * invN;
        float var = Q * invN - mu*mu;
        g_scale[d] = gamma[0] * rsqrtf(var + 1e-5f);  // gamma / sqrt(var + eps)
        float bv = beta[d];
        g_ab[d] = bv + ((d == 0) ? 1.0f : 0.0f);
        if (d == 0) g_ib = 1.0f / (1.0f + bv);
    }
}

// ---------------------------------------------------------------------------
// Pass C: recompute t, scale, transp0(beta), expmap(beta) -> out.
// ---------------------------------------------------------------------------
__global__ void __launch_bounds__(256) passC_kernel(const float* __restrict__ x,
                                                    const float* __restrict__ beta,
                                                    float* __restrict__ out) {
    const int lane = threadIdx.x & 31;
    const int gw   = (blockIdx.x * blockDim.x + threadIdx.x) >> 5;
    const int nw   = (NBLK_C * 256) >> 5;

    float m[8], am[8], sc[8], bt[8], ab[8];
    {
        float4 v;
        v = reinterpret_cast<const float4*>(g_mean)[lane];     m[0]=v.x; m[1]=v.y; m[2]=v.z; m[3]=v.w;
        v = reinterpret_cast<const float4*>(g_mean)[lane+32];  m[4]=v.x; m[5]=v.y; m[6]=v.z; m[7]=v.w;
        v = reinterpret_cast<const float4*>(g_am)[lane];       am[0]=v.x; am[1]=v.y; am[2]=v.z; am[3]=v.w;
        v = reinterpret_cast<const float4*>(g_am)[lane+32];    am[4]=v.x; am[5]=v.y; am[6]=v.z; am[7]=v.w;
        v = reinterpret_cast<const float4*>(g_scale)[lane];    sc[0]=v.x; sc[1]=v.y; sc[2]=v.z; sc[3]=v.w;
        v = reinterpret_cast<const float4*>(g_scale)[lane+32]; sc[4]=v.x; sc[5]=v.y; sc[6]=v.z; sc[7]=v.w;
        v = reinterpret_cast<const float4*>(beta)[lane];       bt[0]=v.x; bt[1]=v.y; bt[2]=v.z; bt[3]=v.w;
        v = reinterpret_cast<const float4*>(beta)[lane+32];    bt[4]=v.x; bt[5]=v.y; bt[6]=v.z; bt[7]=v.w;
        v = reinterpret_cast<const float4*>(g_ab)[lane];       ab[0]=v.x; ab[1]=v.y; ab[2]=v.z; ab[3]=v.w;
        v = reinterpret_cast<const float4*>(g_ab)[lane+32];    ab[4]=v.x; ab[5]=v.y; ab[6]=v.z; ab[7]=v.w;
    }
    const float m0 = g_mean[0];
    const float ic = g_ic;
    const float ib = g_ib;

    for (int row = gw; row < NROWS; row += nw) {
        const float4* rp = reinterpret_cast<const float4*>(x) + (size_t)row * (DDIM/4);
        float xv[8];
        {
            float4 v = rp[lane];    xv[0]=v.x; xv[1]=v.y; xv[2]=v.z; xv[3]=v.w;
            v = rp[lane+32];        xv[4]=v.x; xv[5]=v.y; xv[6]=v.z; xv[7]=v.w;
        }
        // t = transp0back(mean, logmap(mean, x))
        float p = m[0]*xv[0];
        if (lane == 0) p = -p;
        #pragma unroll
        for (int k = 1; k < 8; k++) p += m[k]*xv[k];
        float l = warpsum(p);
        float alpha = fmaxf(-l, 1.0f + 1e-7f);
        float x0 = __shfl_sync(0xffffffffu, xv[0], 0);
        float f = acoshf(alpha) * rsqrtf(alpha*alpha - 1.0f);
        float coef = f * (x0 - alpha*m0) * ic;
        float w[8];
        #pragma unroll
        for (int k = 0; k < 8; k++)
            w[k] = (f*(xv[k] - alpha*m[k]) - coef*am[k]) * sc[k];

        // transp0(beta, w)
        float p2 = bt[0]*w[0];
        if (lane == 0) p2 = -p2;
        #pragma unroll
        for (int k = 1; k < 8; k++) p2 += bt[k]*w[k];
        float lb = warpsum(p2);                  // linner(beta, w)
        float c2 = lb * ib;
        #pragma unroll
        for (int k = 0; k < 8; k++) w[k] += c2*ab[k];

        // expmap(beta, w)
        float p3 = w[0]*w[0];
        if (lane == 0) p3 = -p3;
        #pragma unroll
        for (int k = 1; k < 8; k++) p3 += w[k]*w[k];
        float nn = warpsum(p3);                  // linner(w, w)
        float n  = sqrtf(fmaxf(nn, 1e-7f));
        float ch = coshf(n);
        float sh = sinhf(n) / n;

        float4* op = reinterpret_cast<float4*>(out) + (size_t)row * (DDIM/4);
        op[lane]    = make_float4(ch*bt[0] + sh*w[0], ch*bt[1] + sh*w[1],
                                  ch*bt[2] + sh*w[2], ch*bt[3] + sh*w[3]);
        op[lane+32] = make_float4(ch*bt[4] + sh*w[4], ch*bt[5] + sh*w[5],
                                  ch*bt[6] + sh*w[6], ch*bt[7] + sh*w[7]);
    }
}

// ---------------------------------------------------------------------------
extern "C" void kernel_launch(void* const* d_in, const int* in_sizes, int n_in,
                              void* d_out, int out_size) {
    const float* x     = (const float*)d_in[0];
    const float* beta  = (const float*)d_in[1];
    const float* gamma = (const float*)d_in[2];
    float* out = (float*)d_out;

    dim3 gA(8, BATCH);
    passA_kernel<<<gA, 256>>>(x);
    a2a_kernel<<<BATCH, 256>>>();
    a2b_kernel<<<1, 256>>>();
    passB_kernel<<<NBLK_B, 256>>>(x);
    finB_kernel<<<DDIM, 256>>>(beta, gamma);
    passC_kernel<<<NBLK_C, 256>>>(x, beta, out);
}

// round 3
// speedup vs baseline: 1.6180x; 1.2320x over previous
#include <cuda_runtime.h>
#include <math.h>

#define DDIM   256
#define BATCH  128
#define SEQ    1024
#define NROWS  (BATCH*SEQ)          // 131072
#define HALF   (NROWS/2)            // 65536
#define NBLK_B 1024
#define NBLK_C 2048

// ---- scratch (static device globals; no allocation) ----
__device__ __align__(16) float g_part[8*BATCH*DDIM];   // pass-A partial sums [j][b][d]
__device__ __align__(16) float g_cb[BATCH*DDIM];       // per-batch centroids
__device__ __align__(16) float g_mean[DDIM];
__device__ float g_ic;                                  // 1/(1+mean0)
__device__ __align__(16) float g_bpS[NBLK_B*DDIM];     // pass-B per-block sum(t)
__device__ __align__(16) float g_bpQ[NBLK_B*DDIM];     // pass-B per-block sum(t^2)
__device__ __align__(16) float g_scale[DDIM];          // gamma / sqrt(var+eps)
__device__ float g_ib;                                  // 1/(1+beta0)

__device__ __forceinline__ float warpsum(float v) {
    v += __shfl_xor_sync(0xffffffffu, v, 16);
    v += __shfl_xor_sync(0xffffffffu, v, 8);
    v += __shfl_xor_sync(0xffffffffu, v, 4);
    v += __shfl_xor_sync(0xffffffffu, v, 2);
    v += __shfl_xor_sync(0xffffffffu, v, 1);
    return v;
}

// two interleaved warp reductions (independent shfl chains pipeline)
__device__ __forceinline__ void warpsum2(float& a, float& b) {
    #pragma unroll
    for (int off = 16; off > 0; off >>= 1) {
        a += __shfl_xor_sync(0xffffffffu, a, off);
        b += __shfl_xor_sync(0xffffffffu, b, off);
    }
}

__device__ __forceinline__ float blocksum256(float v, float* sh) {
    const int lane = threadIdx.x & 31;
    const int warp = threadIdx.x >> 5;
    float w = warpsum(v);
    if (lane == 0) sh[warp] = w;
    __syncthreads();
    float r = sh[0];
    #pragma unroll
    for (int i = 1; i < 8; i++) r += sh[i];
    return r;
}

// fast f = acosh(alpha)/sqrt(alpha^2-1)
__device__ __forceinline__ float acosh_over_s(float alpha) {
    float a2m1 = fmaf(alpha, alpha, -1.0f);     // alpha^2 - 1  (>= ~2e-7 after clamp)
    float r = rsqrtf(a2m1);                     // 1/s
    float s = a2m1 * r;                         // s = sqrt(alpha^2-1)
    return __logf(alpha + s) * r;               // acosh(alpha)/s
}

// ---------------------------------------------------------------------------
// Pass A: per-(chunk j, batch b) feature sums over 128 rows of S.
// ---------------------------------------------------------------------------
__global__ void __launch_bounds__(256) passA_kernel(const float* __restrict__ x) {
    const int j = blockIdx.x;
    const int b = blockIdx.y;
    const int d = threadIdx.x;
    const float* p = x + ((size_t)b*SEQ + (size_t)j*128) * DDIM + d;
    float a0=0.f,a1=0.f,a2=0.f,a3=0.f,a4=0.f,a5=0.f,a6=0.f,a7=0.f;
    #pragma unroll 2
    for (int s = 0; s < 128; s += 8) {
        a0 += p[(s+0)*DDIM]; a1 += p[(s+1)*DDIM];
        a2 += p[(s+2)*DDIM]; a3 += p[(s+3)*DDIM];
        a4 += p[(s+4)*DDIM]; a5 += p[(s+5)*DDIM];
        a6 += p[(s+6)*DDIM]; a7 += p[(s+7)*DDIM];
    }
    g_part[((size_t)(j*BATCH + b))*DDIM + d] = ((a0+a1)+(a2+a3)) + ((a4+a5)+(a6+a7));
}

// ---------------------------------------------------------------------------
// A2a: per-batch centroid. grid 128, block 256.
// ---------------------------------------------------------------------------
__global__ void __launch_bounds__(256) a2a_kernel() {
    __shared__ float sh[8];
    const int b = blockIdx.x;
    const int d = threadIdx.x;
    float a = 0.f;
    #pragma unroll
    for (int j = 0; j < 8; j++)
        a += g_part[(size_t)(j*BATCH + b)*DDIM + d];
    a *= (1.0f / (float)SEQ);
    float p = (d == 0) ? -a*a : a*a;
    float l = blocksum256(p, sh);
    float dn = rsqrtf(fmaxf(fabsf(l), 1e-8f));
    g_cb[(size_t)b*DDIM + d] = a * dn;
}

// ---------------------------------------------------------------------------
// A2b: centroid over batch -> g_mean, g_ic. single block 256.
// ---------------------------------------------------------------------------
__global__ void __launch_bounds__(256) a2b_kernel() {
    __shared__ float sh[8];
    const int d = threadIdx.x;
    float a = 0.f;
    #pragma unroll 8
    for (int b = 0; b < BATCH; b++) a += g_cb[(size_t)b*DDIM + d];
    a *= (1.0f / (float)BATCH);
    float p = (d == 0) ? -a*a : a*a;
    float l = blocksum256(p, sh);
    float dn = rsqrtf(fmaxf(fabsf(l), 1e-8f));
    float mv = a * dn;
    g_mean[d] = mv;
    if (d == 0) g_ic = 1.0f / (1.0f + mv);
}

// ---------------------------------------------------------------------------
// Pass B: per-feature Sum(t), Sum(t^2); 2 rows per warp per iteration.
// t_k = f*x_k - (f*alpha + coef)*m_k  (- coef on time comp, lane0 k0)
// ---------------------------------------------------------------------------
__global__ void __launch_bounds__(256) passB_kernel(const float* __restrict__ x) {
    __shared__ float sS[8][DDIM];
    __shared__ float sQ[8][DDIM];
    const int lane = threadIdx.x & 31;
    const int wib  = threadIdx.x >> 5;
    const int gw   = blockIdx.x * 8 + wib;
    const int nw   = NBLK_B * 8;

    float m[8];
    {
        float4 v;
        v = reinterpret_cast<const float4*>(g_mean)[lane];    m[0]=v.x; m[1]=v.y; m[2]=v.z; m[3]=v.w;
        v = reinterpret_cast<const float4*>(g_mean)[lane+32]; m[4]=v.x; m[5]=v.y; m[6]=v.z; m[7]=v.w;
    }
    const float m0 = g_mean[0];
    const float ic = g_ic;

    float sm[8] = {0,0,0,0,0,0,0,0};
    float sq[8] = {0,0,0,0,0,0,0,0};

    for (int row = gw; row < HALF; row += nw) {
        const float4* rp1 = reinterpret_cast<const float4*>(x) + (size_t)row * (DDIM/4);
        const float4* rp2 = rp1 + (size_t)HALF * (DDIM/4);
        float a[8], b[8];
        {
            float4 v1 = rp1[lane], v2 = rp1[lane+32];
            float4 w1 = rp2[lane], w2 = rp2[lane+32];
            a[0]=v1.x; a[1]=v1.y; a[2]=v1.z; a[3]=v1.w;
            a[4]=v2.x; a[5]=v2.y; a[6]=v2.z; a[7]=v2.w;
            b[0]=w1.x; b[1]=w1.y; b[2]=w1.z; b[3]=w1.w;
            b[4]=w2.x; b[5]=w2.y; b[6]=w2.z; b[7]=w2.w;
        }
        float p1 = m[0]*a[0], p2 = m[0]*b[0];
        if (lane == 0) { p1 = -p1; p2 = -p2; }
        #pragma unroll
        for (int k = 1; k < 8; k++) { p1 += m[k]*a[k]; p2 += m[k]*b[k]; }
        warpsum2(p1, p2);
        float al1 = fmaxf(-p1, 1.0f + 1e-7f);
        float al2 = fmaxf(-p2, 1.0f + 1e-7f);
        float x01 = __shfl_sync(0xffffffffu, a[0], 0);
        float x02 = __shfl_sync(0xffffffffu, b[0], 0);
        float f1 = acosh_over_s(al1);
        float f2 = acosh_over_s(al2);
        float c1 = f1 * (x01 - al1*m0) * ic;
        float c2 = f2 * (x02 - al2*m0) * ic;
        float gc1 = fmaf(f1, al1, c1);
        float gc2 = fmaf(f2, al2, c2);
        #pragma unroll
        for (int k = 0; k < 8; k++) {
            float t1 = fmaf(f1, a[k], -gc1*m[k]);
            float t2 = fmaf(f2, b[k], -gc2*m[k]);
            if (k == 0 && lane == 0) { t1 -= c1; t2 -= c2; }
            sm[k] += t1 + t2;
            sq[k] += fmaf(t1, t1, t2*t2);
        }
    }

    const int d0 = lane * 4;
    #pragma unroll
    for (int k = 0; k < 4; k++) {
        sS[wib][d0+k]     = sm[k];   sQ[wib][d0+k]     = sq[k];
        sS[wib][128+d0+k] = sm[4+k]; sQ[wib][128+d0+k] = sq[4+k];
    }
    __syncthreads();
    float accS = 0.f, accQ = 0.f;
    #pragma unroll
    for (int w = 0; w < 8; w++) { accS += sS[w][threadIdx.x]; accQ += sQ[w][threadIdx.x]; }
    g_bpS[(size_t)blockIdx.x*DDIM + threadIdx.x] = accS;
    g_bpQ[(size_t)blockIdx.x*DDIM + threadIdx.x] = accQ;
}

// ---------------------------------------------------------------------------
// finB: fold partials -> scale[d]. grid 256 (feature per block).
// ---------------------------------------------------------------------------
__global__ void __launch_bounds__(256) finB_kernel(const float* __restrict__ beta,
                                                   const float* __restrict__ gamma) {
    __shared__ float shS[8];
    __shared__ float shQ[8];
    const int d   = blockIdx.x;
    const int tid = threadIdx.x;
    const int lane = tid & 31;
    const int warp = tid >> 5;

    float s = 0.f, q = 0.f;
    #pragma unroll
    for (int i = 0; i < NBLK_B/256; i++) {
        int b = i*256 + tid;
        s += g_bpS[(size_t)b*DDIM + d];
        q += g_bpQ[(size_t)b*DDIM + d];
    }
    warpsum2(s, q);
    if (lane == 0) { shS[warp] = s; shQ[warp] = q; }
    __syncthreads();
    if (tid == 0) {
        float S = shS[0], Q = shQ[0];
        #pragma unroll
        for (int i = 1; i < 8; i++) { S += shS[i]; Q += shQ[i]; }
        const float invN = 1.0f / (float)NROWS;
        float mu  = S * invN;
        float var = Q * invN - mu*mu;
        g_scale[d] = gamma[0] * rsqrtf(var + 1e-5f);
        if (d == 0) g_ib = 1.0f / (1.0f + beta[0]);
    }
}

// ---------------------------------------------------------------------------
// Pass C: recompute t, scale, transp0(beta), expmap(beta) -> out.
// 2 rows per warp per iteration.
// ---------------------------------------------------------------------------
__global__ void __launch_bounds__(256) passC_kernel(const float* __restrict__ x,
                                                    const float* __restrict__ beta,
                                                    float* __restrict__ out) {
    const int lane = threadIdx.x & 31;
    const int gw   = (blockIdx.x * blockDim.x + threadIdx.x) >> 5;
    const int nw   = (NBLK_C * 256) >> 5;

    float m[8], sc[8], bt[8];
    {
        float4 v;
        v = reinterpret_cast<const float4*>(g_mean)[lane];     m[0]=v.x; m[1]=v.y; m[2]=v.z; m[3]=v.w;
        v = reinterpret_cast<const float4*>(g_mean)[lane+32];  m[4]=v.x; m[5]=v.y; m[6]=v.z; m[7]=v.w;
        v = reinterpret_cast<const float4*>(g_scale)[lane];    sc[0]=v.x; sc[1]=v.y; sc[2]=v.z; sc[3]=v.w;
        v = reinterpret_cast<const float4*>(g_scale)[lane+32]; sc[4]=v.x; sc[5]=v.y; sc[6]=v.z; sc[7]=v.w;
        v = reinterpret_cast<const float4*>(beta)[lane];       bt[0]=v.x; bt[1]=v.y; bt[2]=v.z; bt[3]=v.w;
        v = reinterpret_cast<const float4*>(beta)[lane+32];    bt[4]=v.x; bt[5]=v.y; bt[6]=v.z; bt[7]=v.w;
    }
    const float m0 = g_mean[0];
    const float ic = g_ic;
    const float ib = g_ib;

    for (int row = gw; row < HALF; row += nw) {
        const float4* rp1 = reinterpret_cast<const float4*>(x) + (size_t)row * (DDIM/4);
        const float4* rp2 = rp1 + (size_t)HALF * (DDIM/4);
        float w1[8], w2[8];
        {
            float4 v1 = rp1[lane], v2 = rp1[lane+32];
            float4 u1 = rp2[lane], u2 = rp2[lane+32];
            w1[0]=v1.x; w1[1]=v1.y; w1[2]=v1.z; w1[3]=v1.w;
            w1[4]=v2.x; w1[5]=v2.y; w1[6]=v2.z; w1[7]=v2.w;
            w2[0]=u1.x; w2[1]=u1.y; w2[2]=u1.z; w2[3]=u1.w;
            w2[4]=u2.x; w2[5]=u2.y; w2[6]=u2.z; w2[7]=u2.w;
        }
        // ---- t = transp0back(mean, logmap(mean, x)), scaled
        float p1 = m[0]*w1[0], p2 = m[0]*w2[0];
        if (lane == 0) { p1 = -p1; p2 = -p2; }
        #pragma unroll
        for (int k = 1; k < 8; k++) { p1 += m[k]*w1[k]; p2 += m[k]*w2[k]; }
        warpsum2(p1, p2);
        float al1 = fmaxf(-p1, 1.0f + 1e-7f);
        float al2 = fmaxf(-p2, 1.0f + 1e-7f);
        float x01 = __shfl_sync(0xffffffffu, w1[0], 0);
        float x02 = __shfl_sync(0xffffffffu, w2[0], 0);
        float f1 = acosh_over_s(al1);
        float f2 = acosh_over_s(al2);
        float c1 = f1 * (x01 - al1*m0) * ic;
        float c2 = f2 * (x02 - al2*m0) * ic;
        float gc1 = fmaf(f1, al1, c1);
        float gc2 = fmaf(f2, al2, c2);
        #pragma unroll
        for (int k = 0; k < 8; k++) {
            float t1 = fmaf(f1, w1[k], -gc1*m[k]);
            float t2 = fmaf(f2, w2[k], -gc2*m[k]);
            if (k == 0 && lane == 0) { t1 -= c1; t2 -= c2; }
            w1[k] = t1 * sc[k];
            w2[k] = t2 * sc[k];
        }
        // ---- transp0(beta, w): w += (linner(beta,w)/(1+b0)) * (beta + e0)
        float q1 = bt[0]*w1[0], q2 = bt[0]*w2[0];
        if (lane == 0) { q1 = -q1; q2 = -q2; }
        #pragma unroll
        for (int k = 1; k < 8; k++) { q1 += bt[k]*w1[k]; q2 += bt[k]*w2[k]; }
        warpsum2(q1, q2);
        float cb1 = q1 * ib, cb2 = q2 * ib;
        #pragma unroll
        for (int k = 0; k < 8; k++) {
            w1[k] = fmaf(cb1, bt[k], w1[k]);
            w2[k] = fmaf(cb2, bt[k], w2[k]);
            if (k == 0 && lane == 0) { w1[0] += cb1; w2[0] += cb2; }
        }
        // ---- expmap(beta, w)
        float n1 = w1[0]*w1[0], n2 = w2[0]*w2[0];
        if (lane == 0) { n1 = -n1; n2 = -n2; }
        #pragma unroll
        for (int k = 1; k < 8; k++) { n1 += w1[k]*w1[k]; n2 += w2[k]*w2[k]; }
        warpsum2(n1, n2);
        float nn1 = sqrtf(fmaxf(n1, 1e-7f));
        float nn2 = sqrtf(fmaxf(n2, 1e-7f));
        float e1 = __expf(nn1), e2 = __expf(nn2);
        float ei1 = __frcp_rn(e1), ei2 = __frcp_rn(e2);
        float ch1 = 0.5f*(e1 + ei1), ch2 = 0.5f*(e2 + ei2);
        float sh1 = 0.5f*(e1 - ei1) * __frcp_rn(nn1);
        float sh2 = 0.5f*(e2 - ei2) * __frcp_rn(nn2);

        float4* op1 = reinterpret_cast<float4*>(out) + (size_t)row * (DDIM/4);
        float4* op2 = op1 + (size_t)HALF * (DDIM/4);
        op1[lane]    = make_float4(fmaf(ch1,bt[0],sh1*w1[0]), fmaf(ch1,bt[1],sh1*w1[1]),
                                   fmaf(ch1,bt[2],sh1*w1[2]), fmaf(ch1,bt[3],sh1*w1[3]));
        op1[lane+32] = make_float4(fmaf(ch1,bt[4],sh1*w1[4]), fmaf(ch1,bt[5],sh1*w1[5]),
                                   fmaf(ch1,bt[6],sh1*w1[6]), fmaf(ch1,bt[7],sh1*w1[7]));
        op2[lane]    = make_float4(fmaf(ch2,bt[0],sh2*w2[0]), fmaf(ch2,bt[1],sh2*w2[1]),
                                   fmaf(ch2,bt[2],sh2*w2[2]), fmaf(ch2,bt[3],sh2*w2[3]));
        op2[lane+32] = make_float4(fmaf(ch2,bt[4],sh2*w2[4]), fmaf(ch2,bt[5],sh2*w2[5]),
                                   fmaf(ch2,bt[6],sh2*w2[6]), fmaf(ch2,bt[7],sh2*w2[7]));
    }
}

// ---------------------------------------------------------------------------
extern "C" void kernel_launch(void* const* d_in, const int* in_sizes, int n_in,
                              void* d_out, int out_size) {
    const float* x     = (const float*)d_in[0];
    const float* beta  = (const float*)d_in[1];
    const float* gamma = (const float*)d_in[2];
    float* out = (float*)d_out;

    dim3 gA(8, BATCH);
    passA_kernel<<<gA, 256>>>(x);
    a2a_kernel<<<BATCH, 256>>>();
    a2b_kernel<<<1, 256>>>();
    passB_kernel<<<NBLK_B, 256>>>(x);
    finB_kernel<<<DDIM, 256>>>(beta, gamma);
    passC_kernel<<<NBLK_C, 256>>>(x, beta, out);
}

// round 4
// speedup vs baseline: 1.6432x; 1.0156x over previous
#include <cuda_runtime.h>
#include <math.h>

#define DDIM   256
#define BATCH  128
#define SEQ    1024
#define NROWS  (BATCH*SEQ)          // 131072
#define HALF   (NROWS/2)            // 65536
#define NBLK_B 512
#define NBLK_C 2048

// ---- scratch (static device globals; no allocation) ----
__device__ __align__(16) float g_part[8*BATCH*DDIM];   // pass-A partial sums [j][b][d]
__device__ __align__(16) float g_cb[BATCH*DDIM];       // per-batch centroids
__device__ __align__(16) float g_mean[DDIM];
__device__ float g_ic;                                  // 1/(1+mean0)
__device__ __align__(16) float g_bpS[NBLK_B*DDIM];     // pass-B per-block sum(t)
__device__ __align__(16) float g_bpQ[NBLK_B*DDIM];     // pass-B per-block sum(t^2)
__device__ __align__(16) float g_scale[DDIM];          // gamma / sqrt(var+eps)
__device__ float g_ib;                                  // 1/(1+beta0)
__device__ float g_lab;                                 // linner(ab,ab) = -2(1+beta0)

__device__ __forceinline__ float warpsum(float v) {
    #pragma unroll
    for (int off = 16; off > 0; off >>= 1)
        v += __shfl_xor_sync(0xffffffffu, v, off);
    return v;
}

__device__ __forceinline__ void warpsum2(float& a, float& b) {
    #pragma unroll
    for (int off = 16; off > 0; off >>= 1) {
        a += __shfl_xor_sync(0xffffffffu, a, off);
        b += __shfl_xor_sync(0xffffffffu, b, off);
    }
}

__device__ __forceinline__ void warpsum4(float& a, float& b, float& c, float& d) {
    #pragma unroll
    for (int off = 16; off > 0; off >>= 1) {
        a += __shfl_xor_sync(0xffffffffu, a, off);
        b += __shfl_xor_sync(0xffffffffu, b, off);
        c += __shfl_xor_sync(0xffffffffu, c, off);
        d += __shfl_xor_sync(0xffffffffu, d, off);
    }
}

__device__ __forceinline__ float blocksum256(float v, float* sh) {
    const int lane = threadIdx.x & 31;
    const int warp = threadIdx.x >> 5;
    float w = warpsum(v);
    if (lane == 0) sh[warp] = w;
    __syncthreads();
    float r = sh[0];
    #pragma unroll
    for (int i = 1; i < 8; i++) r += sh[i];
    return r;
}

// fast f = acosh(alpha)/sqrt(alpha^2-1)
__device__ __forceinline__ float acosh_over_s(float alpha) {
    float a2m1 = fmaf(alpha, alpha, -1.0f);
    float r = rsqrtf(a2m1);
    float s = a2m1 * r;
    return __logf(alpha + s) * r;
}

// ---------------------------------------------------------------------------
// Pass A: per-(chunk j, batch b) feature sums over 128 rows of S. Ascending.
// ---------------------------------------------------------------------------
__global__ void __launch_bounds__(256) passA_kernel(const float* __restrict__ x) {
    const int j = blockIdx.x;
    const int b = blockIdx.y;
    const int d = threadIdx.x;
    const float* p = x + ((size_t)b*SEQ + (size_t)j*128) * DDIM + d;
    float a0=0.f,a1=0.f,a2=0.f,a3=0.f,a4=0.f,a5=0.f,a6=0.f,a7=0.f;
    #pragma unroll 2
    for (int s = 0; s < 128; s += 8) {
        a0 += p[(s+0)*DDIM]; a1 += p[(s+1)*DDIM];
        a2 += p[(s+2)*DDIM]; a3 += p[(s+3)*DDIM];
        a4 += p[(s+4)*DDIM]; a5 += p[(s+5)*DDIM];
        a6 += p[(s+6)*DDIM]; a7 += p[(s+7)*DDIM];
    }
    g_part[((size_t)(j*BATCH + b))*DDIM + d] = ((a0+a1)+(a2+a3)) + ((a4+a5)+(a6+a7));
}

// ---------------------------------------------------------------------------
// A2a: per-batch centroid. grid 128, block 256.
// ---------------------------------------------------------------------------
__global__ void __launch_bounds__(256) a2a_kernel() {
    __shared__ float sh[8];
    const int b = blockIdx.x;
    const int d = threadIdx.x;
    float a = 0.f;
    #pragma unroll
    for (int j = 0; j < 8; j++)
        a += g_part[(size_t)(j*BATCH + b)*DDIM + d];
    a *= (1.0f / (float)SEQ);
    float p = (d == 0) ? -a*a : a*a;
    float l = blocksum256(p, sh);
    float dn = rsqrtf(fmaxf(fabsf(l), 1e-8f));
    g_cb[(size_t)b*DDIM + d] = a * dn;
}

// ---------------------------------------------------------------------------
// A2b: centroid over batch -> g_mean, g_ic. single block 256.
// ---------------------------------------------------------------------------
__global__ void __launch_bounds__(256) a2b_kernel() {
    __shared__ float sh[8];
    const int d = threadIdx.x;
    float a = 0.f;
    #pragma unroll 8
    for (int b = 0; b < BATCH; b++) a += g_cb[(size_t)b*DDIM + d];
    a *= (1.0f / (float)BATCH);
    float p = (d == 0) ? -a*a : a*a;
    float l = blocksum256(p, sh);
    float dn = rsqrtf(fmaxf(fabsf(l), 1e-8f));
    float mv = a * dn;
    g_mean[d] = mv;
    if (d == 0) g_ic = 1.0f / (1.0f + mv);
}

// ---------------------------------------------------------------------------
// Pass B: per-feature Sum(t), Sum(t^2); 2 rows per warp, DESCENDING order
// (serpentine: reuse passA's L2 residue from the top of x).
// ---------------------------------------------------------------------------
__global__ void __launch_bounds__(256) passB_kernel(const float* __restrict__ x) {
    __shared__ float sS[8][DDIM];
    __shared__ float sQ[8][DDIM];
    const int lane = threadIdx.x & 31;
    const int wib  = threadIdx.x >> 5;
    const int gw   = blockIdx.x * 8 + wib;
    const int nw   = NBLK_B * 8;

    float m[8];
    {
        float4 v;
        v = reinterpret_cast<const float4*>(g_mean)[lane];    m[0]=v.x; m[1]=v.y; m[2]=v.z; m[3]=v.w;
        v = reinterpret_cast<const float4*>(g_mean)[lane+32]; m[4]=v.x; m[5]=v.y; m[6]=v.z; m[7]=v.w;
    }
    const float m0 = g_mean[0];
    const float ic = g_ic;

    float sm[8] = {0,0,0,0,0,0,0,0};
    float sq[8] = {0,0,0,0,0,0,0,0};

    for (int idx = gw; idx < HALF; idx += nw) {
        const int row = HALF - 1 - idx;            // descending
        const float4* rp1 = reinterpret_cast<const float4*>(x) + (size_t)row * (DDIM/4);
        const float4* rp2 = rp1 + (size_t)HALF * (DDIM/4);
        float a[8], b[8];
        {
            float4 v1 = rp1[lane], v2 = rp1[lane+32];
            float4 w1 = rp2[lane], w2 = rp2[lane+32];
            a[0]=v1.x; a[1]=v1.y; a[2]=v1.z; a[3]=v1.w;
            a[4]=v2.x; a[5]=v2.y; a[6]=v2.z; a[7]=v2.w;
            b[0]=w1.x; b[1]=w1.y; b[2]=w1.z; b[3]=w1.w;
            b[4]=w2.x; b[5]=w2.y; b[6]=w2.z; b[7]=w2.w;
        }
        float p1 = m[0]*a[0], p2 = m[0]*b[0];
        if (lane == 0) { p1 = -p1; p2 = -p2; }
        #pragma unroll
        for (int k = 1; k < 8; k++) { p1 += m[k]*a[k]; p2 += m[k]*b[k]; }
        warpsum2(p1, p2);
        float al1 = fmaxf(-p1, 1.0f + 1e-7f);
        float al2 = fmaxf(-p2, 1.0f + 1e-7f);
        float x01 = __shfl_sync(0xffffffffu, a[0], 0);
        float x02 = __shfl_sync(0xffffffffu, b[0], 0);
        float f1 = acosh_over_s(al1);
        float f2 = acosh_over_s(al2);
        float c1 = f1 * (x01 - al1*m0) * ic;
        float c2 = f2 * (x02 - al2*m0) * ic;
        float gc1 = fmaf(f1, al1, c1);
        float gc2 = fmaf(f2, al2, c2);
        #pragma unroll
        for (int k = 0; k < 8; k++) {
            float t1 = fmaf(f1, a[k], -gc1*m[k]);
            float t2 = fmaf(f2, b[k], -gc2*m[k]);
            if (k == 0 && lane == 0) { t1 -= c1; t2 -= c2; }
            sm[k] += t1 + t2;
            sq[k] += fmaf(t1, t1, t2*t2);
        }
    }

    const int d0 = lane * 4;
    #pragma unroll
    for (int k = 0; k < 4; k++) {
        sS[wib][d0+k]     = sm[k];   sQ[wib][d0+k]     = sq[k];
        sS[wib][128+d0+k] = sm[4+k]; sQ[wib][128+d0+k] = sq[4+k];
    }
    __syncthreads();
    float accS = 0.f, accQ = 0.f;
    #pragma unroll
    for (int w = 0; w < 8; w++) { accS += sS[w][threadIdx.x]; accQ += sQ[w][threadIdx.x]; }
    g_bpS[(size_t)blockIdx.x*DDIM + threadIdx.x] = accS;
    g_bpQ[(size_t)blockIdx.x*DDIM + threadIdx.x] = accQ;
}

// ---------------------------------------------------------------------------
// finB: fold partials -> scale[d]. grid 256 (feature per block).
// ---------------------------------------------------------------------------
__global__ void __launch_bounds__(256) finB_kernel(const float* __restrict__ beta,
                                                   const float* __restrict__ gamma) {
    __shared__ float shS[8];
    __shared__ float shQ[8];
    const int d   = blockIdx.x;
    const int tid = threadIdx.x;
    const int lane = tid & 31;
    const int warp = tid >> 5;

    float s = 0.f, q = 0.f;
    #pragma unroll
    for (int i = 0; i < NBLK_B/256; i++) {
        int b = i*256 + tid;
        s += g_bpS[(size_t)b*DDIM + d];
        q += g_bpQ[(size_t)b*DDIM + d];
    }
    warpsum2(s, q);
    if (lane == 0) { shS[warp] = s; shQ[warp] = q; }
    __syncthreads();
    if (tid == 0) {
        float S = shS[0], Q = shQ[0];
        #pragma unroll
        for (int i = 1; i < 8; i++) { S += shS[i]; Q += shQ[i]; }
        const float invN = 1.0f / (float)NROWS;
        float mu  = S * invN;
        float var = Q * invN - mu*mu;
        g_scale[d] = gamma[0] * rsqrtf(var + 1e-5f);
        if (d == 0) {
            float b0 = beta[0];
            g_ib  = 1.0f / (1.0f + b0);
            g_lab = -2.0f * (1.0f + b0);
        }
    }
}

// ---------------------------------------------------------------------------
// Pass C: recompute t, scale, transp0(beta), expmap(beta) -> out.
// 2 rows/warp, ASCENDING (hits B's L2 residue at the bottom of x).
// Fused reductions: q=linner(beta,w), nw=linner(w,w) in ONE warpsum batch;
// post-transport norm computed analytically:
//   n^2 = nw + 2*cb*(q - w_t) + cb^2 * lab,  cb=q*ib, lab=-2(1+b0).
// __ldcs on x (last use), __stcs on out (no L2 pollution).
// ---------------------------------------------------------------------------
__global__ void __launch_bounds__(256) passC_kernel(const float* __restrict__ x,
                                                    const float* __restrict__ beta,
                                                    float* __restrict__ out) {
    const int lane = threadIdx.x & 31;
    const int gw   = (blockIdx.x * blockDim.x + threadIdx.x) >> 5;
    const int nw_  = (NBLK_C * 256) >> 5;

    float m[8], sc[8], bt[8];
    {
        float4 v;
        v = reinterpret_cast<const float4*>(g_mean)[lane];     m[0]=v.x; m[1]=v.y; m[2]=v.z; m[3]=v.w;
        v = reinterpret_cast<const float4*>(g_mean)[lane+32];  m[4]=v.x; m[5]=v.y; m[6]=v.z; m[7]=v.w;
        v = reinterpret_cast<const float4*>(g_scale)[lane];    sc[0]=v.x; sc[1]=v.y; sc[2]=v.z; sc[3]=v.w;
        v = reinterpret_cast<const float4*>(g_scale)[lane+32]; sc[4]=v.x; sc[5]=v.y; sc[6]=v.z; sc[7]=v.w;
        v = reinterpret_cast<const float4*>(beta)[lane];       bt[0]=v.x; bt[1]=v.y; bt[2]=v.z; bt[3]=v.w;
        v = reinterpret_cast<const float4*>(beta)[lane+32];    bt[4]=v.x; bt[5]=v.y; bt[6]=v.z; bt[7]=v.w;
    }
    const float m0  = g_mean[0];
    const float ic  = g_ic;
    const float ib  = g_ib;
    const float lab = g_lab;

    for (int row = gw; row < HALF; row += nw_) {
        const float4* rp1 = reinterpret_cast<const float4*>(x) + (size_t)row * (DDIM/4);
        const float4* rp2 = rp1 + (size_t)HALF * (DDIM/4);
        float w1[8], w2[8];
        {
            float4 v1 = __ldcs(rp1 + lane), v2 = __ldcs(rp1 + lane + 32);
            float4 u1 = __ldcs(rp2 + lane), u2 = __ldcs(rp2 + lane + 32);
            w1[0]=v1.x; w1[1]=v1.y; w1[2]=v1.z; w1[3]=v1.w;
            w1[4]=v2.x; w1[5]=v2.y; w1[6]=v2.z; w1[7]=v2.w;
            w2[0]=u1.x; w2[1]=u1.y; w2[2]=u1.z; w2[3]=u1.w;
            w2[4]=u2.x; w2[5]=u2.y; w2[6]=u2.z; w2[7]=u2.w;
        }
        // ---- t = transp0back(mean, logmap(mean, x)), scaled
        float p1 = m[0]*w1[0], p2 = m[0]*w2[0];
        if (lane == 0) { p1 = -p1; p2 = -p2; }
        #pragma unroll
        for (int k = 1; k < 8; k++) { p1 += m[k]*w1[k]; p2 += m[k]*w2[k]; }
        warpsum2(p1, p2);
        float al1 = fmaxf(-p1, 1.0f + 1e-7f);
        float al2 = fmaxf(-p2, 1.0f + 1e-7f);
        float x01 = __shfl_sync(0xffffffffu, w1[0], 0);
        float x02 = __shfl_sync(0xffffffffu, w2[0], 0);
        float f1 = acosh_over_s(al1);
        float f2 = acosh_over_s(al2);
        float c1 = f1 * (x01 - al1*m0) * ic;
        float c2 = f2 * (x02 - al2*m0) * ic;
        float gc1 = fmaf(f1, al1, c1);
        float gc2 = fmaf(f2, al2, c2);
        #pragma unroll
        for (int k = 0; k < 8; k++) {
            float t1 = fmaf(f1, w1[k], -gc1*m[k]);
            float t2 = fmaf(f2, w2[k], -gc2*m[k]);
            if (k == 0 && lane == 0) { t1 -= c1; t2 -= c2; }
            w1[k] = t1 * sc[k];
            w2[k] = t2 * sc[k];
        }
        // w time components (lane 0 of k=0), broadcast
        float wt1 = __shfl_sync(0xffffffffu, w1[0], 0);
        float wt2 = __shfl_sync(0xffffffffu, w2[0], 0);

        // ---- fused: q = linner(beta,w), nw = linner(w,w) in one batch
        float q1 = bt[0]*w1[0], q2 = bt[0]*w2[0];
        float n1 = w1[0]*w1[0], n2 = w2[0]*w2[0];
        if (lane == 0) { q1 = -q1; q2 = -q2; n1 = -n1; n2 = -n2; }
        #pragma unroll
        for (int k = 1; k < 8; k++) {
            q1 += bt[k]*w1[k]; q2 += bt[k]*w2[k];
            n1 += w1[k]*w1[k]; n2 += w2[k]*w2[k];
        }
        warpsum4(q1, n1, q2, n2);

        float cb1 = q1 * ib, cb2 = q2 * ib;
        float nn2_1 = n1 + 2.0f*cb1*(q1 - wt1) + cb1*cb1*lab;
        float nn2_2 = n2 + 2.0f*cb2*(q2 - wt2) + cb2*cb2*lab;
        float nn1 = sqrtf(fmaxf(nn2_1, 1e-7f));
        float nn2 = sqrtf(fmaxf(nn2_2, 1e-7f));
        float e1 = __expf(nn1), e2 = __expf(nn2);
        float ei1 = __frcp_rn(e1), ei2 = __frcp_rn(e2);
        float ch1 = 0.5f*(e1 + ei1), ch2 = 0.5f*(e2 + ei2);
        float sh1 = 0.5f*(e1 - ei1) * __frcp_rn(nn1);
        float sh2 = 0.5f*(e2 - ei2) * __frcp_rn(nn2);

        // w' = w + cb*(beta + e0); out = ch*beta + sh*w'
        #pragma unroll
        for (int k = 0; k < 8; k++) {
            w1[k] = fmaf(cb1, bt[k], w1[k]);
            w2[k] = fmaf(cb2, bt[k], w2[k]);
            if (k == 0 && lane == 0) { w1[0] += cb1; w2[0] += cb2; }
        }

        float4* op1 = reinterpret_cast<float4*>(out) + (size_t)row * (DDIM/4);
        float4* op2 = op1 + (size_t)HALF * (DDIM/4);
        __stcs(op1 + lane,      make_float4(fmaf(ch1,bt[0],sh1*w1[0]), fmaf(ch1,bt[1],sh1*w1[1]),
                                            fmaf(ch1,bt[2],sh1*w1[2]), fmaf(ch1,bt[3],sh1*w1[3])));
        __stcs(op1 + lane + 32, make_float4(fmaf(ch1,bt[4],sh1*w1[4]), fmaf(ch1,bt[5],sh1*w1[5]),
                                            fmaf(ch1,bt[6],sh1*w1[6]), fmaf(ch1,bt[7],sh1*w1[7])));
        __stcs(op2 + lane,      make_float4(fmaf(ch2,bt[0],sh2*w2[0]), fmaf(ch2,bt[1],sh2*w2[1]),
                                            fmaf(ch2,bt[2],sh2*w2[2]), fmaf(ch2,bt[3],sh2*w2[3])));
        __stcs(op2 + lane + 32, make_float4(fmaf(ch2,bt[4],sh2*w2[4]), fmaf(ch2,bt[5],sh2*w2[5]),
                                            fmaf(ch2,bt[6],sh2*w2[6]), fmaf(ch2,bt[7],sh2*w2[7])));
    }
}

// ---------------------------------------------------------------------------
extern "C" void kernel_launch(void* const* d_in, const int* in_sizes, int n_in,
                              void* d_out, int out_size) {
    const float* x     = (const float*)d_in[0];
    const float* beta  = (const float*)d_in[1];
    const float* gamma = (const float*)d_in[2];
    float* out = (float*)d_out;

    dim3 gA(8, BATCH);
    passA_kernel<<<gA, 256>>>(x);
    a2a_kernel<<<BATCH, 256>>>();
    a2b_kernel<<<1, 256>>>();
    passB_kernel<<<NBLK_B, 256>>>(x);
    finB_kernel<<<DDIM, 256>>>(beta, gamma);
    passC_kernel<<<NBLK_C, 256>>>(x, beta, out);
}